// round 9
// baseline (speedup 1.0000x reference)
#include <cuda_runtime.h>
#include <cuda_bf16.h>
#include <cstdint>

// Problem constants (fixed shapes from reference)
#define BB 4
#define TT 2048
#define CC 1024
#define NH 16
#define HS 64
#define NQKV 3072
#define MROWS (BB*TT)          // 8192

// Scratch (device globals: allocation-free rule)
__device__ float g_qkv[(size_t)MROWS * NQKV];
__device__ float g_y[(size_t)MROWS * CC];
__device__ float g_xr[(size_t)MROWS * CC];
__device__ float g_wattn[(size_t)CC * NQKV];
__device__ float g_wproj[(size_t)CC * CC];

// ---------------------------------------------------------------------------
__device__ __forceinline__ float to_tf32(float f) {
    uint32_t u;
    asm("cvt.rna.tf32.f32 %0, %1;" : "=r"(u) : "f"(f));
    return __uint_as_float(u);
}
__device__ __forceinline__ uint32_t to_tf32_bits(float f) {
    uint32_t u;
    asm("cvt.rna.tf32.f32 %0, %1;" : "=r"(u) : "f"(f));
    return u;
}

__global__ void round_tf32_kernel(const float* __restrict__ in,
                                  float* __restrict__ out, int n4)
{
    int i = blockIdx.x * blockDim.x + threadIdx.x;
    if (i < n4) {
        float4 v = reinterpret_cast<const float4*>(in)[i];
        v.x = to_tf32(v.x); v.y = to_tf32(v.y);
        v.z = to_tf32(v.z); v.w = to_tf32(v.w);
        reinterpret_cast<float4*>(out)[i] = v;
    }
}

// ---------------------------------------------------------------------------
// TF32 tensor-core GEMM, 3-stage cp.async pipeline, per-kb fragment loads
// (lower register pressure so 2 CTAs/SM genuinely fit).
// 128x128 tile, GBK=16, 256 threads, warp tile 64x32.
// ---------------------------------------------------------------------------
#define GBM 128
#define GBN 128
#define GBK 16
#define SA 20
#define SB 136
#define NSTAGE 3
#define AS_STRIDE (GBM * SA)   // 2560 floats
#define BS_STRIDE (GBK * SB)   // 2176 floats
#define GEMM_SMEM_BYTES (NSTAGE * (AS_STRIDE + BS_STRIDE) * 4)   // 56832

__device__ __forceinline__ void cp16(void* dst, const void* src) {
    unsigned d = (unsigned)__cvta_generic_to_shared(dst);
    asm volatile("cp.async.cg.shared.global [%0], [%1], 16;\n" :: "r"(d), "l"(src));
}

__device__ __forceinline__ void mma_tf32(float* c, const uint32_t* a, const uint32_t* b) {
    asm volatile(
        "mma.sync.aligned.m16n8k8.row.col.f32.tf32.tf32.f32 "
        "{%0,%1,%2,%3}, {%4,%5,%6,%7}, {%8,%9}, {%0,%1,%2,%3};\n"
        : "+f"(c[0]), "+f"(c[1]), "+f"(c[2]), "+f"(c[3])
        : "r"(a[0]), "r"(a[1]), "r"(a[2]), "r"(a[3]), "r"(b[0]), "r"(b[1]));
}

__global__ __launch_bounds__(256, 2)
void sgemm_tf32_kernel(const float* __restrict__ A, const float* __restrict__ W,
                       const float* __restrict__ bias, const float* __restrict__ wpe,
                       float* __restrict__ Cout, int M, int N, int K, int addPos)
{
    extern __shared__ float smem[];
    float* Asm = smem;
    float* Bsm = smem + NSTAGE * AS_STRIDE;

    const int tid  = threadIdx.x;
    const int brow = blockIdx.y;
    const int bcol = blockIdx.x;

    const int w    = tid >> 5;
    const int lane = tid & 31;
    const int g    = lane >> 2;
    const int kk   = lane & 3;
    const int m_warp = (w >> 2) * 64;
    const int n_warp = (w & 3) * 32;

    const float* Aptr = A + (size_t)brow * GBM * K;
    const float* Wptr = W + (size_t)bcol * GBN;

    float acc[4][4][4];
#pragma unroll
    for (int i = 0; i < 4; i++)
#pragma unroll
        for (int j = 0; j < 4; j++)
#pragma unroll
            for (int t = 0; t < 4; t++) acc[i][j][t] = 0.f;

    auto load_stage = [&](int s, int k0) {
        float* As = Asm + s * AS_STRIDE;
        float* Bs = Bsm + s * BS_STRIDE;
#pragma unroll
        for (int c = tid; c < 512; c += 256) {
            int row = c >> 2, kp = (c & 3) << 2;
            cp16(&As[row * SA + kp], Aptr + (size_t)row * K + k0 + kp);
            int kr = c >> 5, np = (c & 31) << 2;
            cp16(&Bs[kr * SB + np], Wptr + (size_t)(k0 + kr) * N + np);
        }
    };

    const int niter = K / GBK;
    load_stage(0, 0);
    asm volatile("cp.async.commit_group;\n");
    load_stage(1, GBK);
    asm volatile("cp.async.commit_group;\n");
    asm volatile("cp.async.wait_group 1;\n");   // stage 0 ready
    __syncthreads();

    for (int it = 0; it < niter; it++) {
        const int s = it % NSTAGE;
        const uint32_t* as = reinterpret_cast<const uint32_t*>(Asm + s * AS_STRIDE);
        const uint32_t* bs = reinterpret_cast<const uint32_t*>(Bsm + s * BS_STRIDE);

        // prefetch stage it+2 (overlaps with fragment LDS + MMA below)
        bool committed = false;
        if (it + 2 < niter) {
            load_stage((it + 2) % NSTAGE, (it + 2) * GBK);
            asm volatile("cp.async.commit_group;\n");
            committed = true;
        }

#pragma unroll
        for (int kb = 0; kb < GBK; kb += 8) {
            uint32_t afr[4][4], bfr[4][2];
#pragma unroll
            for (int ms = 0; ms < 4; ms++) {
                int m0 = m_warp + ms * 16 + g;
                afr[ms][0] = as[(m0)     * SA + kb + kk];
                afr[ms][1] = as[(m0 + 8) * SA + kb + kk];
                afr[ms][2] = as[(m0)     * SA + kb + kk + 4];
                afr[ms][3] = as[(m0 + 8) * SA + kb + kk + 4];
            }
#pragma unroll
            for (int ns = 0; ns < 4; ns++) {
                int n0 = n_warp + ns * 8 + g;
                bfr[ns][0] = bs[(kb + kk)     * SB + n0];
                bfr[ns][1] = bs[(kb + kk + 4) * SB + n0];
            }
#pragma unroll
            for (int ms = 0; ms < 4; ms++)
#pragma unroll
                for (int ns = 0; ns < 4; ns++)
                    mma_tf32(acc[ms][ns], afr[ms], bfr[ns]);
        }

        if (committed) {
            asm volatile("cp.async.wait_group 1;\n");
        } else {
            asm volatile("cp.async.wait_group 0;\n");
        }
        __syncthreads();
    }

    // Epilogue: bias (+ wpe on q,k columns): q[b,t,h,d] += wpe[(t*16+h)&2047][d]
#pragma unroll
    for (int ms = 0; ms < 4; ms++) {
#pragma unroll
        for (int ns = 0; ns < 4; ns++) {
#pragma unroll
            for (int half = 0; half < 2; half++) {
                int rl  = m_warp + ms * 16 + g + half * 8;
                int row = brow * GBM + rl;
                int t   = row & (TT - 1);
                int cl  = n_warp + ns * 8 + kk * 2;
                int col = bcol * GBN + cl;
                float v0 = acc[ms][ns][half * 2 + 0] + bias[col];
                float v1 = acc[ms][ns][half * 2 + 1] + bias[col + 1];
                if (addPos && col < 2 * CC) {
                    int cc = col & (CC - 1);
                    int h  = cc >> 6;
                    int d  = cc & 63;
                    const float* wr = wpe + (size_t)((((t << 4) + h) & (TT - 1))) * HS;
                    v0 += wr[d];
                    v1 += wr[d + 1];
                }
                float2 o = make_float2(v0, v1);
                *reinterpret_cast<float2*>(Cout + (size_t)row * N + col) = o;
            }
        }
    }
}

// ---------------------------------------------------------------------------
// Tensor-core (tf32 mma) causal flash attention. 2 CTAs/SM target.
// ---------------------------------------------------------------------------
#define FA_BM 128
#define FA_BN 32
#define KS_S 68
#define VS_S 72
#define PS_S 36
#define FNEG (-1.0e30f)

__global__ __launch_bounds__(256, 2)
void attn_tc_kernel(const float* __restrict__ qkv, float* __restrict__ y)
{
    __shared__ float Ks[FA_BN * KS_S];
    __shared__ float Vs[FA_BN * VS_S];
    __shared__ float Ps[8][16 * PS_S];

    const int tid  = threadIdx.x;
    const int w    = tid >> 5;
    const int lane = tid & 31;
    const int g    = lane >> 2;
    const int kk   = lane & 3;

    const int qtile = (gridDim.x - 1) - blockIdx.x;
    const int bh    = blockIdx.y;
    const int b     = bh >> 4;
    const int h     = bh & 15;

    const int qb = qtile * FA_BM;
    const float* qptr = qkv + (size_t)b * TT * NQKV + h * HS;
    const float* kptr = qptr + CC;
    const float* vptr = qptr + 2 * CC;

    const int wrow0 = qb + w * 16;
    const int row0  = wrow0 + g;
    const int row1  = row0 + 8;

    uint32_t qfr[8][4];
    {
        const float* q0 = qptr + (size_t)row0 * NQKV;
        const float* q1 = qptr + (size_t)row1 * NQKV;
#pragma unroll
        for (int kc = 0; kc < 8; kc++) {
            qfr[kc][0] = to_tf32_bits(q0[kc * 8 + kk]     * 0.125f);
            qfr[kc][1] = to_tf32_bits(q1[kc * 8 + kk]     * 0.125f);
            qfr[kc][2] = to_tf32_bits(q0[kc * 8 + kk + 4] * 0.125f);
            qfr[kc][3] = to_tf32_bits(q1[kc * 8 + kk + 4] * 0.125f);
        }
    }

    float oacc[8][4];
#pragma unroll
    for (int nt = 0; nt < 8; nt++)
#pragma unroll
        for (int t = 0; t < 4; t++) oacc[nt][t] = 0.f;

    float m0 = FNEG, m1 = FNEG, l0 = 0.f, l1 = 0.f;

    const uint32_t* Ksb = reinterpret_cast<const uint32_t*>(Ks);
    const uint32_t* Vsb = reinterpret_cast<const uint32_t*>(Vs);
    const uint32_t* Psb = reinterpret_cast<const uint32_t*>(Ps[w]);

    const int nkt = (qb + FA_BM) / FA_BN;
    for (int kt = 0; kt < nkt; kt++) {
        const int kb = kt * FA_BN;

        __syncthreads();
#pragma unroll
        for (int c = tid; c < 512; c += 256) {
            int rr = c >> 4;
            int d4 = (c & 15) << 2;
            float4 k4 = *reinterpret_cast<const float4*>(kptr + (size_t)(kb + rr) * NQKV + d4);
            float4 v4 = *reinterpret_cast<const float4*>(vptr + (size_t)(kb + rr) * NQKV + d4);
            float* kd = &Ks[rr * KS_S + d4];
            kd[0] = to_tf32(k4.x); kd[1] = to_tf32(k4.y);
            kd[2] = to_tf32(k4.z); kd[3] = to_tf32(k4.w);
            float* vd = &Vs[rr * VS_S + d4];
            vd[0] = to_tf32(v4.x); vd[1] = to_tf32(v4.y);
            vd[2] = to_tf32(v4.z); vd[3] = to_tf32(v4.w);
        }
        __syncthreads();

        if (kb <= wrow0 + 15) {
            float sacc[4][4];
#pragma unroll
            for (int nt = 0; nt < 4; nt++)
#pragma unroll
                for (int t = 0; t < 4; t++) sacc[nt][t] = 0.f;

#pragma unroll
            for (int kc = 0; kc < 8; kc++) {
#pragma unroll
                for (int nt = 0; nt < 4; nt++) {
                    uint32_t bfr[2];
                    bfr[0] = Ksb[(nt * 8 + g) * KS_S + kc * 8 + kk];
                    bfr[1] = Ksb[(nt * 8 + g) * KS_S + kc * 8 + kk + 4];
                    mma_tf32(sacc[nt], qfr[kc], bfr);
                }
            }

            float mx0 = FNEG, mx1 = FNEG;
#pragma unroll
            for (int nt = 0; nt < 4; nt++) {
                int c0 = kb + nt * 8 + 2 * kk;
                if (c0     > row0) sacc[nt][0] = FNEG;
                if (c0 + 1 > row0) sacc[nt][1] = FNEG;
                if (c0     > row1) sacc[nt][2] = FNEG;
                if (c0 + 1 > row1) sacc[nt][3] = FNEG;
                mx0 = fmaxf(mx0, fmaxf(sacc[nt][0], sacc[nt][1]));
                mx1 = fmaxf(mx1, fmaxf(sacc[nt][2], sacc[nt][3]));
            }
            mx0 = fmaxf(mx0, __shfl_xor_sync(0xffffffffu, mx0, 1));
            mx0 = fmaxf(mx0, __shfl_xor_sync(0xffffffffu, mx0, 2));
            mx1 = fmaxf(mx1, __shfl_xor_sync(0xffffffffu, mx1, 1));
            mx1 = fmaxf(mx1, __shfl_xor_sync(0xffffffffu, mx1, 2));

            float m0n = fmaxf(m0, mx0), m1n = fmaxf(m1, mx1);
            float a0 = __expf(m0 - m0n), a1 = __expf(m1 - m1n);

            float ps0 = 0.f, ps1 = 0.f;
            float* Pw = Ps[w];
#pragma unroll
            for (int nt = 0; nt < 4; nt++) {
                float p0 = __expf(sacc[nt][0] - m0n);
                float p1 = __expf(sacc[nt][1] - m0n);
                float p2 = __expf(sacc[nt][2] - m1n);
                float p3 = __expf(sacc[nt][3] - m1n);
                ps0 += p0 + p1;
                ps1 += p2 + p3;
                int cl = nt * 8 + 2 * kk;
                Pw[(g)     * PS_S + cl]     = to_tf32(p0);
                Pw[(g)     * PS_S + cl + 1] = to_tf32(p1);
                Pw[(g + 8) * PS_S + cl]     = to_tf32(p2);
                Pw[(g + 8) * PS_S + cl + 1] = to_tf32(p3);
            }
            ps0 += __shfl_xor_sync(0xffffffffu, ps0, 1);
            ps0 += __shfl_xor_sync(0xffffffffu, ps0, 2);
            ps1 += __shfl_xor_sync(0xffffffffu, ps1, 1);
            ps1 += __shfl_xor_sync(0xffffffffu, ps1, 2);

            l0 = l0 * a0 + ps0;
            l1 = l1 * a1 + ps1;
            m0 = m0n; m1 = m1n;

#pragma unroll
            for (int nt = 0; nt < 8; nt++) {
                oacc[nt][0] *= a0; oacc[nt][1] *= a0;
                oacc[nt][2] *= a1; oacc[nt][3] *= a1;
            }
            __syncwarp();

#pragma unroll
            for (int kc = 0; kc < 4; kc++) {
                uint32_t afr[4];
                afr[0] = Psb[(g)     * PS_S + kc * 8 + kk];
                afr[1] = Psb[(g + 8) * PS_S + kc * 8 + kk];
                afr[2] = Psb[(g)     * PS_S + kc * 8 + kk + 4];
                afr[3] = Psb[(g + 8) * PS_S + kc * 8 + kk + 4];
#pragma unroll
                for (int nt = 0; nt < 8; nt++) {
                    uint32_t bfr[2];
                    bfr[0] = Vsb[(kc * 8 + kk)     * VS_S + nt * 8 + g];
                    bfr[1] = Vsb[(kc * 8 + kk + 4) * VS_S + nt * 8 + g];
                    mma_tf32(oacc[nt], afr, bfr);
                }
            }
        }
    }

    float inv0 = 1.f / l0, inv1 = 1.f / l1;
    float* y0 = y + (size_t)(b * TT + row0) * CC + h * HS;
    float* y1 = y + (size_t)(b * TT + row1) * CC + h * HS;
#pragma unroll
    for (int nt = 0; nt < 8; nt++) {
        int cl = nt * 8 + 2 * kk;
        float2 o0 = make_float2(to_tf32(oacc[nt][0] * inv0), to_tf32(oacc[nt][1] * inv0));
        float2 o1 = make_float2(to_tf32(oacc[nt][2] * inv1), to_tf32(oacc[nt][3] * inv1));
        *reinterpret_cast<float2*>(y0 + cl) = o0;
        *reinterpret_cast<float2*>(y1 + cl) = o1;
    }
}

// ---------------------------------------------------------------------------
extern "C" void kernel_launch(void* const* d_in, const int* in_sizes, int n_in,
                              void* d_out, int out_size)
{
    const float* x        = (const float*)d_in[0];
    const float* c_attn_w = (const float*)d_in[1];
    const float* c_attn_b = (const float*)d_in[2];
    const float* c_proj_w = (const float*)d_in[3];
    const float* c_proj_b = (const float*)d_in[4];
    const float* wpe      = (const float*)d_in[5];
    float* out = (float*)d_out;

    float *qkv = nullptr, *y = nullptr, *xr = nullptr, *wa = nullptr, *wp = nullptr;
    cudaGetSymbolAddress((void**)&qkv, g_qkv);
    cudaGetSymbolAddress((void**)&y,   g_y);
    cudaGetSymbolAddress((void**)&xr,  g_xr);
    cudaGetSymbolAddress((void**)&wa,  g_wattn);
    cudaGetSymbolAddress((void**)&wp,  g_wproj);

    static bool attr_set = false;
    if (!attr_set) {
        cudaFuncSetAttribute(sgemm_tf32_kernel,
                             cudaFuncAttributeMaxDynamicSharedMemorySize,
                             GEMM_SMEM_BYTES);
        // max smem carveout so TWO 56.8KB CTAs can co-reside per SM
        cudaFuncSetAttribute(sgemm_tf32_kernel,
                             cudaFuncAttributePreferredSharedMemoryCarveout, 100);
        cudaFuncSetAttribute(attn_tc_kernel,
                             cudaFuncAttributePreferredSharedMemoryCarveout, 100);
        attr_set = true;
    }

    // 0) round A/W operands to tf32 (rna)
    {
        int n4 = (MROWS * CC) / 4;
        round_tf32_kernel<<<(n4 + 255) / 256, 256>>>(x, xr, n4);
        n4 = (CC * NQKV) / 4;
        round_tf32_kernel<<<(n4 + 255) / 256, 256>>>(c_attn_w, wa, n4);
        n4 = (CC * CC) / 4;
        round_tf32_kernel<<<(n4 + 255) / 256, 256>>>(c_proj_w, wp, n4);
    }

    // 1) qkv = x @ c_attn_w + b (+ wpe on q,k)
    dim3 g1(NQKV / GBN, MROWS / GBM);
    sgemm_tf32_kernel<<<g1, 256, GEMM_SMEM_BYTES>>>(xr, wa, c_attn_b, wpe, qkv,
                                                    MROWS, NQKV, CC, 1);

    // 2) causal flash attention
    attn_tc_kernel<<<dim3(TT / FA_BM, BB * NH), 256>>>(qkv, y);

    // 3) out = y @ c_proj_w + c_proj_b
    dim3 g2(CC / GBN, MROWS / GBM);
    sgemm_tf32_kernel<<<g2, 256, GEMM_SMEM_BYTES>>>(y, wp, c_proj_b, nullptr, out,
                                                    MROWS, CC, CC, 0);
}

// round 10
// speedup vs baseline: 1.0524x; 1.0524x over previous
#include <cuda_runtime.h>
#include <cuda_bf16.h>
#include <cstdint>

// Problem constants (fixed shapes from reference)
#define BB 4
#define TT 2048
#define CC 1024
#define NH 16
#define HS 64
#define NQKV 3072
#define MROWS (BB*TT)          // 8192

// Scratch (device globals: allocation-free rule)
__device__ float g_qkv[(size_t)MROWS * NQKV];
__device__ float g_y[(size_t)MROWS * CC];
__device__ float g_xr[(size_t)MROWS * CC];
__device__ float g_wattn[(size_t)CC * NQKV];
__device__ float g_wproj[(size_t)CC * CC];

// ---------------------------------------------------------------------------
__device__ __forceinline__ float to_tf32(float f) {
    uint32_t u;
    asm("cvt.rna.tf32.f32 %0, %1;" : "=r"(u) : "f"(f));
    return __uint_as_float(u);
}
__device__ __forceinline__ uint32_t to_tf32_bits(float f) {
    uint32_t u;
    asm("cvt.rna.tf32.f32 %0, %1;" : "=r"(u) : "f"(f));
    return u;
}

__global__ void round_tf32_kernel(const float* __restrict__ in,
                                  float* __restrict__ out, int n4)
{
    int i = blockIdx.x * blockDim.x + threadIdx.x;
    if (i < n4) {
        float4 v = reinterpret_cast<const float4*>(in)[i];
        v.x = to_tf32(v.x); v.y = to_tf32(v.y);
        v.z = to_tf32(v.z); v.w = to_tf32(v.w);
        reinterpret_cast<float4*>(out)[i] = v;
    }
}

// ---------------------------------------------------------------------------
// TF32 tensor-core GEMM, SMALL-CTA variant for multi-CTA/SM overlap:
// 128 threads (4 warps), CTA tile 64x128, warp tile 32x64 (2x2 warp grid),
// GBK=16, 3-stage cp.async pipeline. ~110-128 regs -> 3-4 CTAs/SM.
// ---------------------------------------------------------------------------
#define GBM 64
#define GBN 128
#define GBK 16
#define SA 20
#define SB 136
#define NSTAGE 3
#define AS_STRIDE (GBM * SA)   // 1280 floats
#define BS_STRIDE (GBK * SB)   // 2176 floats
#define GEMM_SMEM_BYTES (NSTAGE * (AS_STRIDE + BS_STRIDE) * 4)   // 41472

__device__ __forceinline__ void cp16(void* dst, const void* src) {
    unsigned d = (unsigned)__cvta_generic_to_shared(dst);
    asm volatile("cp.async.cg.shared.global [%0], [%1], 16;\n" :: "r"(d), "l"(src));
}

__device__ __forceinline__ void mma_tf32(float* c, const uint32_t* a, const uint32_t* b) {
    asm volatile(
        "mma.sync.aligned.m16n8k8.row.col.f32.tf32.tf32.f32 "
        "{%0,%1,%2,%3}, {%4,%5,%6,%7}, {%8,%9}, {%0,%1,%2,%3};\n"
        : "+f"(c[0]), "+f"(c[1]), "+f"(c[2]), "+f"(c[3])
        : "r"(a[0]), "r"(a[1]), "r"(a[2]), "r"(a[3]), "r"(b[0]), "r"(b[1]));
}

__global__ __launch_bounds__(128, 4)
void sgemm_tf32_kernel(const float* __restrict__ A, const float* __restrict__ W,
                       const float* __restrict__ bias, const float* __restrict__ wpe,
                       float* __restrict__ Cout, int M, int N, int K, int addPos)
{
    extern __shared__ float smem[];
    float* Asm = smem;
    float* Bsm = smem + NSTAGE * AS_STRIDE;

    const int tid  = threadIdx.x;        // 0..127
    const int brow = blockIdx.y;
    const int bcol = blockIdx.x;

    const int w    = tid >> 5;           // 0..3
    const int lane = tid & 31;
    const int g    = lane >> 2;          // 0..7
    const int kk   = lane & 3;           // 0..3
    const int m_warp = (w >> 1) * 32;    // 0 or 32
    const int n_warp = (w & 1) * 64;     // 0 or 64

    const float* Aptr = A + (size_t)brow * GBM * K;
    const float* Wptr = W + (size_t)bcol * GBN;

    float acc[2][8][4];
#pragma unroll
    for (int i = 0; i < 2; i++)
#pragma unroll
        for (int j = 0; j < 8; j++)
#pragma unroll
            for (int t = 0; t < 4; t++) acc[i][j][t] = 0.f;

    auto load_stage = [&](int s, int k0) {
        float* As = Asm + s * AS_STRIDE;
        float* Bs = Bsm + s * BS_STRIDE;
        // A tile: 64 rows x 16 k = 256 16B chunks
#pragma unroll
        for (int c = tid; c < 256; c += 128) {
            int row = c >> 2, kp = (c & 3) << 2;
            cp16(&As[row * SA + kp], Aptr + (size_t)row * K + k0 + kp);
        }
        // B tile: 16 k x 128 n = 512 16B chunks
#pragma unroll
        for (int c = tid; c < 512; c += 128) {
            int kr = c >> 5, np = (c & 31) << 2;
            cp16(&Bs[kr * SB + np], Wptr + (size_t)(k0 + kr) * N + np);
        }
    };

    const int niter = K / GBK;
    load_stage(0, 0);
    asm volatile("cp.async.commit_group;\n");
    load_stage(1, GBK);
    asm volatile("cp.async.commit_group;\n");
    asm volatile("cp.async.wait_group 1;\n");   // stage 0 ready
    __syncthreads();

    for (int it = 0; it < niter; it++) {
        const int s = it % NSTAGE;
        const uint32_t* as = reinterpret_cast<const uint32_t*>(Asm + s * AS_STRIDE);
        const uint32_t* bs = reinterpret_cast<const uint32_t*>(Bsm + s * BS_STRIDE);

        // prefetch stage it+2 (overlaps with fragment LDS + MMA below)
        bool committed = false;
        if (it + 2 < niter) {
            load_stage((it + 2) % NSTAGE, (it + 2) * GBK);
            asm volatile("cp.async.commit_group;\n");
            committed = true;
        }

#pragma unroll
        for (int kb = 0; kb < GBK; kb += 8) {
            uint32_t afr[2][4], bfr[8][2];
#pragma unroll
            for (int ms = 0; ms < 2; ms++) {
                int m0 = m_warp + ms * 16 + g;
                afr[ms][0] = as[(m0)     * SA + kb + kk];
                afr[ms][1] = as[(m0 + 8) * SA + kb + kk];
                afr[ms][2] = as[(m0)     * SA + kb + kk + 4];
                afr[ms][3] = as[(m0 + 8) * SA + kb + kk + 4];
            }
#pragma unroll
            for (int ns = 0; ns < 8; ns++) {
                int n0 = n_warp + ns * 8 + g;
                bfr[ns][0] = bs[(kb + kk)     * SB + n0];
                bfr[ns][1] = bs[(kb + kk + 4) * SB + n0];
            }
#pragma unroll
            for (int ms = 0; ms < 2; ms++)
#pragma unroll
                for (int ns = 0; ns < 8; ns++)
                    mma_tf32(acc[ms][ns], afr[ms], bfr[ns]);
        }

        if (committed) {
            asm volatile("cp.async.wait_group 1;\n");
        } else {
            asm volatile("cp.async.wait_group 0;\n");
        }
        __syncthreads();
    }

    // Epilogue: bias (+ wpe on q,k columns): q[b,t,h,d] += wpe[(t*16+h)&2047][d]
#pragma unroll
    for (int ms = 0; ms < 2; ms++) {
#pragma unroll
        for (int ns = 0; ns < 8; ns++) {
#pragma unroll
            for (int half = 0; half < 2; half++) {
                int rl  = m_warp + ms * 16 + g + half * 8;
                int row = brow * GBM + rl;
                int t   = row & (TT - 1);
                int cl  = n_warp + ns * 8 + kk * 2;
                int col = bcol * GBN + cl;
                float v0 = acc[ms][ns][half * 2 + 0] + bias[col];
                float v1 = acc[ms][ns][half * 2 + 1] + bias[col + 1];
                if (addPos && col < 2 * CC) {
                    int cc = col & (CC - 1);
                    int h  = cc >> 6;
                    int d  = cc & 63;
                    const float* wr = wpe + (size_t)((((t << 4) + h) & (TT - 1))) * HS;
                    v0 += wr[d];
                    v1 += wr[d + 1];
                }
                float2 o = make_float2(v0, v1);
                *reinterpret_cast<float2*>(Cout + (size_t)row * N + col) = o;
            }
        }
    }
}

// ---------------------------------------------------------------------------
// Tensor-core (tf32 mma) causal flash attention. (unchanged — control)
// ---------------------------------------------------------------------------
#define FA_BM 128
#define FA_BN 32
#define KS_S 68
#define VS_S 72
#define PS_S 36
#define FNEG (-1.0e30f)

__global__ __launch_bounds__(256, 2)
void attn_tc_kernel(const float* __restrict__ qkv, float* __restrict__ y)
{
    __shared__ float Ks[FA_BN * KS_S];
    __shared__ float Vs[FA_BN * VS_S];
    __shared__ float Ps[8][16 * PS_S];

    const int tid  = threadIdx.x;
    const int w    = tid >> 5;
    const int lane = tid & 31;
    const int g    = lane >> 2;
    const int kk   = lane & 3;

    const int qtile = (gridDim.x - 1) - blockIdx.x;
    const int bh    = blockIdx.y;
    const int b     = bh >> 4;
    const int h     = bh & 15;

    const int qb = qtile * FA_BM;
    const float* qptr = qkv + (size_t)b * TT * NQKV + h * HS;
    const float* kptr = qptr + CC;
    const float* vptr = qptr + 2 * CC;

    const int wrow0 = qb + w * 16;
    const int row0  = wrow0 + g;
    const int row1  = row0 + 8;

    uint32_t qfr[8][4];
    {
        const float* q0 = qptr + (size_t)row0 * NQKV;
        const float* q1 = qptr + (size_t)row1 * NQKV;
#pragma unroll
        for (int kc = 0; kc < 8; kc++) {
            qfr[kc][0] = to_tf32_bits(q0[kc * 8 + kk]     * 0.125f);
            qfr[kc][1] = to_tf32_bits(q1[kc * 8 + kk]     * 0.125f);
            qfr[kc][2] = to_tf32_bits(q0[kc * 8 + kk + 4] * 0.125f);
            qfr[kc][3] = to_tf32_bits(q1[kc * 8 + kk + 4] * 0.125f);
        }
    }

    float oacc[8][4];
#pragma unroll
    for (int nt = 0; nt < 8; nt++)
#pragma unroll
        for (int t = 0; t < 4; t++) oacc[nt][t] = 0.f;

    float m0 = FNEG, m1 = FNEG, l0 = 0.f, l1 = 0.f;

    const uint32_t* Ksb = reinterpret_cast<const uint32_t*>(Ks);
    const uint32_t* Vsb = reinterpret_cast<const uint32_t*>(Vs);
    const uint32_t* Psb = reinterpret_cast<const uint32_t*>(Ps[w]);

    const int nkt = (qb + FA_BM) / FA_BN;
    for (int kt = 0; kt < nkt; kt++) {
        const int kb = kt * FA_BN;

        __syncthreads();
#pragma unroll
        for (int c = tid; c < 512; c += 256) {
            int rr = c >> 4;
            int d4 = (c & 15) << 2;
            float4 k4 = *reinterpret_cast<const float4*>(kptr + (size_t)(kb + rr) * NQKV + d4);
            float4 v4 = *reinterpret_cast<const float4*>(vptr + (size_t)(kb + rr) * NQKV + d4);
            float* kd = &Ks[rr * KS_S + d4];
            kd[0] = to_tf32(k4.x); kd[1] = to_tf32(k4.y);
            kd[2] = to_tf32(k4.z); kd[3] = to_tf32(k4.w);
            float* vd = &Vs[rr * VS_S + d4];
            vd[0] = to_tf32(v4.x); vd[1] = to_tf32(v4.y);
            vd[2] = to_tf32(v4.z); vd[3] = to_tf32(v4.w);
        }
        __syncthreads();

        if (kb <= wrow0 + 15) {
            float sacc[4][4];
#pragma unroll
            for (int nt = 0; nt < 4; nt++)
#pragma unroll
                for (int t = 0; t < 4; t++) sacc[nt][t] = 0.f;

#pragma unroll
            for (int kc = 0; kc < 8; kc++) {
#pragma unroll
                for (int nt = 0; nt < 4; nt++) {
                    uint32_t bfr[2];
                    bfr[0] = Ksb[(nt * 8 + g) * KS_S + kc * 8 + kk];
                    bfr[1] = Ksb[(nt * 8 + g) * KS_S + kc * 8 + kk + 4];
                    mma_tf32(sacc[nt], qfr[kc], bfr);
                }
            }

            float mx0 = FNEG, mx1 = FNEG;
#pragma unroll
            for (int nt = 0; nt < 4; nt++) {
                int c0 = kb + nt * 8 + 2 * kk;
                if (c0     > row0) sacc[nt][0] = FNEG;
                if (c0 + 1 > row0) sacc[nt][1] = FNEG;
                if (c0     > row1) sacc[nt][2] = FNEG;
                if (c0 + 1 > row1) sacc[nt][3] = FNEG;
                mx0 = fmaxf(mx0, fmaxf(sacc[nt][0], sacc[nt][1]));
                mx1 = fmaxf(mx1, fmaxf(sacc[nt][2], sacc[nt][3]));
            }
            mx0 = fmaxf(mx0, __shfl_xor_sync(0xffffffffu, mx0, 1));
            mx0 = fmaxf(mx0, __shfl_xor_sync(0xffffffffu, mx0, 2));
            mx1 = fmaxf(mx1, __shfl_xor_sync(0xffffffffu, mx1, 1));
            mx1 = fmaxf(mx1, __shfl_xor_sync(0xffffffffu, mx1, 2));

            float m0n = fmaxf(m0, mx0), m1n = fmaxf(m1, mx1);
            float a0 = __expf(m0 - m0n), a1 = __expf(m1 - m1n);

            float ps0 = 0.f, ps1 = 0.f;
            float* Pw = Ps[w];
#pragma unroll
            for (int nt = 0; nt < 4; nt++) {
                float p0 = __expf(sacc[nt][0] - m0n);
                float p1 = __expf(sacc[nt][1] - m0n);
                float p2 = __expf(sacc[nt][2] - m1n);
                float p3 = __expf(sacc[nt][3] - m1n);
                ps0 += p0 + p1;
                ps1 += p2 + p3;
                int cl = nt * 8 + 2 * kk;
                Pw[(g)     * PS_S + cl]     = to_tf32(p0);
                Pw[(g)     * PS_S + cl + 1] = to_tf32(p1);
                Pw[(g + 8) * PS_S + cl]     = to_tf32(p2);
                Pw[(g + 8) * PS_S + cl + 1] = to_tf32(p3);
            }
            ps0 += __shfl_xor_sync(0xffffffffu, ps0, 1);
            ps0 += __shfl_xor_sync(0xffffffffu, ps0, 2);
            ps1 += __shfl_xor_sync(0xffffffffu, ps1, 1);
            ps1 += __shfl_xor_sync(0xffffffffu, ps1, 2);

            l0 = l0 * a0 + ps0;
            l1 = l1 * a1 + ps1;
            m0 = m0n; m1 = m1n;

#pragma unroll
            for (int nt = 0; nt < 8; nt++) {
                oacc[nt][0] *= a0; oacc[nt][1] *= a0;
                oacc[nt][2] *= a1; oacc[nt][3] *= a1;
            }
            __syncwarp();

#pragma unroll
            for (int kc = 0; kc < 4; kc++) {
                uint32_t afr[4];
                afr[0] = Psb[(g)     * PS_S + kc * 8 + kk];
                afr[1] = Psb[(g + 8) * PS_S + kc * 8 + kk];
                afr[2] = Psb[(g)     * PS_S + kc * 8 + kk + 4];
                afr[3] = Psb[(g + 8) * PS_S + kc * 8 + kk + 4];
#pragma unroll
                for (int nt = 0; nt < 8; nt++) {
                    uint32_t bfr[2];
                    bfr[0] = Vsb[(kc * 8 + kk)     * VS_S + nt * 8 + g];
                    bfr[1] = Vsb[(kc * 8 + kk + 4) * VS_S + nt * 8 + g];
                    mma_tf32(oacc[nt], afr, bfr);
                }
            }
        }
    }

    float inv0 = 1.f / l0, inv1 = 1.f / l1;
    float* y0 = y + (size_t)(b * TT + row0) * CC + h * HS;
    float* y1 = y + (size_t)(b * TT + row1) * CC + h * HS;
#pragma unroll
    for (int nt = 0; nt < 8; nt++) {
        int cl = nt * 8 + 2 * kk;
        float2 o0 = make_float2(to_tf32(oacc[nt][0] * inv0), to_tf32(oacc[nt][1] * inv0));
        float2 o1 = make_float2(to_tf32(oacc[nt][2] * inv1), to_tf32(oacc[nt][3] * inv1));
        *reinterpret_cast<float2*>(y0 + cl) = o0;
        *reinterpret_cast<float2*>(y1 + cl) = o1;
    }
}

// ---------------------------------------------------------------------------
extern "C" void kernel_launch(void* const* d_in, const int* in_sizes, int n_in,
                              void* d_out, int out_size)
{
    const float* x        = (const float*)d_in[0];
    const float* c_attn_w = (const float*)d_in[1];
    const float* c_attn_b = (const float*)d_in[2];
    const float* c_proj_w = (const float*)d_in[3];
    const float* c_proj_b = (const float*)d_in[4];
    const float* wpe      = (const float*)d_in[5];
    float* out = (float*)d_out;

    float *qkv = nullptr, *y = nullptr, *xr = nullptr, *wa = nullptr, *wp = nullptr;
    cudaGetSymbolAddress((void**)&qkv, g_qkv);
    cudaGetSymbolAddress((void**)&y,   g_y);
    cudaGetSymbolAddress((void**)&xr,  g_xr);
    cudaGetSymbolAddress((void**)&wa,  g_wattn);
    cudaGetSymbolAddress((void**)&wp,  g_wproj);

    static bool attr_set = false;
    if (!attr_set) {
        cudaFuncSetAttribute(sgemm_tf32_kernel,
                             cudaFuncAttributeMaxDynamicSharedMemorySize,
                             GEMM_SMEM_BYTES);
        cudaFuncSetAttribute(sgemm_tf32_kernel,
                             cudaFuncAttributePreferredSharedMemoryCarveout, 100);
        cudaFuncSetAttribute(attn_tc_kernel,
                             cudaFuncAttributePreferredSharedMemoryCarveout, 100);
        attr_set = true;
    }

    // 0) round A/W operands to tf32 (rna)
    {
        int n4 = (MROWS * CC) / 4;
        round_tf32_kernel<<<(n4 + 255) / 256, 256>>>(x, xr, n4);
        n4 = (CC * NQKV) / 4;
        round_tf32_kernel<<<(n4 + 255) / 256, 256>>>(c_attn_w, wa, n4);
        n4 = (CC * CC) / 4;
        round_tf32_kernel<<<(n4 + 255) / 256, 256>>>(c_proj_w, wp, n4);
    }

    // 1) qkv = x @ c_attn_w + b (+ wpe on q,k)
    dim3 g1(NQKV / GBN, MROWS / GBM);
    sgemm_tf32_kernel<<<g1, 128, GEMM_SMEM_BYTES>>>(xr, wa, c_attn_b, wpe, qkv,
                                                    MROWS, NQKV, CC, 1);

    // 2) causal flash attention
    attn_tc_kernel<<<dim3(TT / FA_BM, BB * NH), 256>>>(qkv, y);

    // 3) out = y @ c_proj_w + c_proj_b
    dim3 g2(CC / GBN, MROWS / GBM);
    sgemm_tf32_kernel<<<g2, 128, GEMM_SMEM_BYTES>>>(y, wp, c_proj_b, nullptr, out,
                                                    MROWS, CC, CC, 0);
}